// round 13
// baseline (speedup 1.0000x reference)
#include <cuda_runtime.h>
#include <cstdint>
#include <math.h>

#define T      1024
#define LRC    0.01f

#define SFQ   1048            // sF row stride in floats (20 pad + 1024 + 4 tail)
#define NF4   262             // float4 per sF row
#define SW0   8384            // cw region start (floats) = 8*SFQ
#define RSEG  6144            // reduction floats per sub-group (16*128+16*256)
#define SMEMF 16576           // total dyn smem floats = SW0 + 8*1024

// Scratch (device globals — allocation is forbidden)
__device__ float g_part[256];          // per-CTA err-dot partials (overwritten each launch)
__device__ unsigned int g_bar;         // monotonic grid barrier (never reset)

extern __shared__ float smem[];

// ---------------------------------------------------------------------------
// Single fused kernel. grid (32 pair-tiles, 4 e, 2 rs-halves) = 256 CTAs,
// 640 thr, 2 CTAs/SM guaranteed -> all CTAs resident -> grid spin-barrier OK.
//   pre-barrier : err-dot partial (64 thr) + Fx staging + out-zero/gamma
//   barrier     : monotonic atomic counter (replay-safe, no reset)
//   post-barrier: fixed-order err sum -> cw rows into smem -> conv ->
//                 overlay reduce -> atomicAdd out (2 contributors: determ.)
// ---------------------------------------------------------------------------
__global__ void __launch_bounds__(640, 2)
kfused(const float* __restrict__ Fx, const float* __restrict__ Dis,
       const float* __restrict__ w0, float* __restrict__ out) {
    __shared__ float sP[2];
    __shared__ float sE[4][2];
    __shared__ float sErr[4];

    const int tid  = threadIdx.x;
    const int b    = blockIdx.x;
    const int e    = blockIdx.y;
    const int half = blockIdx.z;
    const int lin  = (half << 7) + (e << 5) + b;    // 0..255

    const float4* fx4 = (const float4*)Fx;
    const float4* w04 = (const float4*)w0;
    const float4 z4 = make_float4(0.f, 0.f, 0.f, 0.f);

    // ---- phase 1a: this CTA's err-dot partial (task = (rs, quarter, ee)) ----
    if (tid < 64) {
        const int rs = lin >> 4, q4 = (lin >> 2) & 3, ee = lin & 3;
        const int base = (q4 << 6) + tid;           // float4 index in quarter
        const float4 x = fx4[(((rs << 2) + ee) << 8) + base];
        const float4 w = w04[(rs << 8) + base];
        float v = x.x * w.x + x.y * w.y + x.z * w.z + x.w * w.w;
#pragma unroll
        for (int o = 16; o; o >>= 1) v += __shfl_xor_sync(0xffffffffu, v, o);
        if ((tid & 31) == 0) sP[tid >> 5] = v;
    }

    // ---- phase 1b: out zero-init (lin<4) and gamma (lin 4..7) ----
    if (lin < 4) {
        if (tid < 256) ((float4*)out)[(lin << 8) + tid] = z4;
    } else if (lin < 8) {
        if (tid < 256) {
            const int g = ((lin - 4) << 8) + tid;
            out[4096 + g] = __expf((float)(1023 - g) * -1.0005003e-3f);
        }
    }

    // ---- phase 1c: stage this half's 8 Fx rows (front zero-padded) ----
    float4* dF = (float4*)smem;
    for (int idx = tid; idx < 8 * NF4; idx += 640) {
        const int qq = idx / NF4, i = idx - qq * NF4;
        float4 v = z4;
        if (i >= 5 && i < 261)
            v = fx4[(((((half << 3) + qq) << 2) + e) << 8) + i - 5];
        dF[qq * NF4 + i] = v;
    }
    __syncthreads();

    // ---- grid barrier (monotonic, replay-safe) ----
    if (tid == 0) {
        g_part[lin] = sP[0] + sP[1];
        __threadfence();                             // release (cumulative)
        const unsigned int old = atomicAdd(&g_bar, 1u);
        const unsigned int target = (old & ~255u) + 256u;
        while (*(volatile unsigned int*)&g_bar < target) { }
    }
    __syncthreads();
    __threadfence();                                 // acquire side

    // ---- phase 2: fixed-order err sums ----
    if (tid < 256) {
        const int eo = tid >> 6, idx = tid & 63;
        const int rs = idx >> 2, q4 = idx & 3;
        float v = g_part[(rs << 4) + (q4 << 2) + eo];
#pragma unroll
        for (int o = 16; o; o >>= 1) v += __shfl_xor_sync(0xffffffffu, v, o);
        if ((tid & 31) == 0) sE[eo][(tid >> 5) & 1] = v;
    }
    __syncthreads();
    if (tid < 4)
        sErr[tid] = Dis[tid * T + (T - 1)] - (sE[tid][0] + sE[tid][1]);
    __syncthreads();

    // ---- phase 3: this half's 8 cw rows straight into smem ----
    {
        const float er0 = sErr[0], er1 = sErr[1], er2 = sErr[2], er3 = sErr[3];
        float4* sW4 = (float4*)(smem + SW0);
        for (int idx = tid; idx < 2048; idx += 640) {
            const int r = idx >> 8, c4 = idx & 255;
            const int rs = (half << 3) + r;
            float4 c = w04[(rs << 8) + c4];
            const float4 x0 = fx4[(((rs << 2) + 0) << 8) + c4];
            const float4 x1 = fx4[(((rs << 2) + 1) << 8) + c4];
            const float4 x2 = fx4[(((rs << 2) + 2) << 8) + c4];
            const float4 x3 = fx4[(((rs << 2) + 3) << 8) + c4];
            c.x += LRC * (x0.x * er0 + x1.x * er1 + x2.x * er2 + x3.x * er3);
            c.y += LRC * (x0.y * er0 + x1.y * er1 + x2.y * er2 + x3.y * er3);
            c.z += LRC * (x0.z * er0 + x1.z * er1 + x2.z * er2 + x3.z * er3);
            c.w += LRC * (x0.w * er0 + x1.w * er1 + x2.w * er2 + x3.w * er3);
            sW4[idx] = c;
        }
    }
    __syncthreads();

    // ---- phase 4: conv (R11 geometry: 2 sub-groups of 320 thr x 4 rs rows) ----
    const int sub  = (tid >= 320);
    const int tloc = tid - (sub << 8) - (sub << 6);
    const int t0A = b << 4, t0B = (63 - b) << 4;
    const int cA = (b + 1) << 2;                    // 4..128 chunks for tile A
    const int cB = 260 - cA;                        // chunks for tile B
    const bool active = tloc < 260;
    const bool isA = tloc < cA;
    const int t0 = isA ? t0A : t0B;
    const int nb = (isA ? tloc : (tloc - cA)) << 2;
    const int ab = 16 + t0 - nb;

    float acc[16];
#pragma unroll
    for (int j = 0; j < 16; j++) acc[j] = 0.f;

    if (active) {
        const float* wB = &smem[SW0 + ((sub << 2) << 10) + nb];
        const float* fBase = &smem[(sub << 2) * SFQ + ab];
#pragma unroll
        for (int qq = 0; qq < 4; qq++) {
            const float4 w = *(const float4*)(wB + (qq << 10));
            const float4* F4 = (const float4*)(fBase + qq * SFQ);
            float ff[24];
#pragma unroll
            for (int m = 0; m < 6; m++) {
                const float4 v = F4[m];
                ff[4 * m + 0] = v.x; ff[4 * m + 1] = v.y;
                ff[4 * m + 2] = v.z; ff[4 * m + 3] = v.w;
            }
#pragma unroll
            for (int j = 0; j < 16; j++)
                acc[j] += ff[4 + j] * w.x + ff[3 + j] * w.y
                        + ff[2 + j] * w.z + ff[1 + j] * w.w;
        }
    }
    __syncthreads();

    // ---- phase 5: overlay partials onto smem ----
    float* redA = smem + sub * RSEG;                // [16][128]
    float* redB = redA + 16 * 128;                  // [16][256]
    if (active) {
        if (isA) {
#pragma unroll
            for (int j = 0; j < 16; j++) redA[j * 128 + tloc] = acc[j];
        } else {
#pragma unroll
            for (int j = 0; j < 16; j++) redB[j * 256 + (tloc - cA)] = acc[j];
        }
    }
    __syncthreads();

    // ---- phase 6: reduce 32 rows x 16 lanes + shuffle -> atomicAdd out ----
    if (tid < 512) {
        const int row = tid >> 4, k = tid & 15;
        float s = 0.f;
        if (row < 16) {
            for (int c = k; c < cA; c += 16)
                s += smem[row * 128 + c] + smem[RSEG + row * 128 + c];
        } else {
            const int r2 = row - 16;
            for (int c = k; c < cB; c += 16)
                s += smem[2048 + r2 * 256 + c] + smem[RSEG + 2048 + r2 * 256 + c];
        }
#pragma unroll
        for (int o = 8; o; o >>= 1) s += __shfl_xor_sync(0xffffffffu, s, o);

        if (k == 0) {
            const int t = (row < 16) ? (t0A + row) : (t0B + row - 16);
            atomicAdd(&out[(t << 2) + e], s);       // 2 contributors: determ.
        }
    }
}

// ---------------------------------------------------------------------------
extern "C" void kernel_launch(void* const* d_in, const int* in_sizes, int n_in,
                              void* d_out, int out_size) {
    const float* Fx  = (const float*)d_in[0];   // [4,4,4,1024]
    const float* Dis = (const float*)d_in[1];   // [4,1024]
    const float* w0  = (const float*)d_in[2];   // [4,4,1024]
    float* out = (float*)d_out;                 // [1024*4 anti | 1024 gamma]

    const size_t dynBytes = (size_t)SMEMF * sizeof(float);   // 66,304 B
    cudaFuncSetAttribute(kfused, cudaFuncAttributeMaxDynamicSharedMemorySize,
                         (int)dynBytes);
    kfused<<<dim3(32, 4, 2), 640, dynBytes>>>(Fx, Dis, w0, out);
}

// round 14
// speedup vs baseline: 1.1775x; 1.1775x over previous
#include <cuda_runtime.h>
#include <cstdint>
#include <math.h>

#define T      1024
#define LRC    0.01f

// Scratch (device globals — allocation is forbidden)
__device__ float g_cw[16 * T];      // control weights [rs, n]
__device__ float g_epart[32];       // 8 cluster ranks x 4 e partials

// ---------------------------------------------------------------------------
// k1 (8-CTA cluster, 256 thr/CTA): fused err + cw + gamma + out zero-init.
// Fires the PDL trigger immediately so k2 can start staging Fx in parallel.
// Fx/w0 values register-cached across phases A and B (read global ONCE).
// Dis prefetched to smem before the barrier. gamma/zero fill the barrier gap.
// ---------------------------------------------------------------------------
__global__ void __cluster_dims__(8, 1, 1) k1(const float* __restrict__ Fx,
                                             const float* __restrict__ Dis,
                                             const float* __restrict__ w0,
                                             float* __restrict__ out) {
    asm volatile("griddepcontrol.launch_dependents;");

    const int tid  = threadIdx.x;
    const int rank = blockIdx.x;
    const float4* w4  = (const float4*)w0;
    const float4* fx4 = (const float4*)Fx;

    __shared__ float sp[8][4];
    __shared__ float serr[4];
    __shared__ float sDis[4];

    // prefetch Dis[e, 1023] (off the post-barrier critical path)
    if (tid < 4) sDis[tid] = Dis[tid * T + (T - 1)];

    // ---- phase A: err-dot partials; cache all operands in registers ----
    float4 wv[2];
    float4 xv[2][4];
    float acc[4] = {0.f, 0.f, 0.f, 0.f};
#pragma unroll
    for (int s = 0; s < 2; s++) {
        const int i4 = rank * 512 + s * 256 + tid;    // float4 index into w0
        wv[s] = w4[i4];
        const int rs = i4 >> 8, n4 = i4 & 255;
#pragma unroll
        for (int e = 0; e < 4; e++) {
            const float4 x = fx4[(rs << 10) + (e << 8) + n4];
            xv[s][e] = x;
            acc[e] += x.x * wv[s].x + x.y * wv[s].y + x.z * wv[s].z + x.w * wv[s].w;
        }
    }
#pragma unroll
    for (int o = 16; o; o >>= 1)
#pragma unroll
        for (int e = 0; e < 4; e++) acc[e] += __shfl_xor_sync(0xffffffffu, acc[e], o);

    if ((tid & 31) == 0)
#pragma unroll
        for (int e = 0; e < 4; e++) sp[tid >> 5][e] = acc[e];
    __syncthreads();
    if (tid < 4) {
        float s = 0.f;
#pragma unroll
        for (int wq = 0; wq < 8; wq++) s += sp[wq][tid];
        g_epart[rank * 4 + tid] = s;
    }

    asm volatile("barrier.cluster.arrive.release.aligned;" ::: "memory");

    // ---- barrier gap: zero out[0:4096) + gamma vector (independent work) ----
    {
        const int g = rank * 256 + tid;               // 0..2047
        if (g < 1024) {
            ((float4*)out)[g] = make_float4(0.f, 0.f, 0.f, 0.f);
            out[4096 + g] = __expf((float)(1023 - g) * -1.0005003e-3f);
        }
    }

    asm volatile("barrier.cluster.wait.acquire.aligned;" ::: "memory");

    if (tid < 4) {
        volatile const float* gp = g_epart;
        float s = 0.f;
#pragma unroll
        for (int r = 0; r < 8; r++) s += gp[r * 4 + tid];
        serr[tid] = sDis[tid] - s;
    }
    __syncthreads();
    const float e0 = serr[0], e1 = serr[1], e2 = serr[2], e3 = serr[3];

    // ---- phase B: cw from the register-cached operands (no reloads) ----
    float4* cw4 = (float4*)g_cw;
#pragma unroll
    for (int s = 0; s < 2; s++) {
        const int i4 = rank * 512 + s * 256 + tid;
        float4 c = wv[s];
        c.x += LRC * (xv[s][0].x * e0 + xv[s][1].x * e1 + xv[s][2].x * e2 + xv[s][3].x * e3);
        c.y += LRC * (xv[s][0].y * e0 + xv[s][1].y * e1 + xv[s][2].y * e2 + xv[s][3].y * e3);
        c.z += LRC * (xv[s][0].z * e0 + xv[s][1].z * e1 + xv[s][2].z * e2 + xv[s][3].z * e3);
        c.w += LRC * (xv[s][0].w * e0 + xv[s][1].w * e1 + xv[s][2].w * e2 + xv[s][3].w * e3);
        cw4[i4] = c;
    }
}

// ---------------------------------------------------------------------------
// k2 (identical to the proven R11 version): causal correlation.
// grid (32 pair-tiles, 4 e, 2 rs-halves) = 256 CTAs, 640 thr, 2 CTAs/SM,
// ONE wave. cw read via __ldg (L2-hot), PDL wait directly before compute.
// Reduction: overlay -> 32 rows x 16 lanes + shuffle -> atomicAdd out
// (exactly 2 contributors per element -> deterministic).
// ---------------------------------------------------------------------------
#define SFQ   1048            // sF row stride in floats (20 pad + 1024 + 4 tail)
#define NF4   262             // float4 per sF row
#define RSEG  6144            // reduction floats per sub-group (16*128+16*256)

extern __shared__ float smem[];

__global__ void __launch_bounds__(640, 2)
k2(const float* __restrict__ Fx, float* __restrict__ out) {
    const int tid  = threadIdx.x;
    const int b    = blockIdx.x;
    const int e    = blockIdx.y;
    const int half = blockIdx.z;                    // rs-half
    const int sub  = (tid >= 320);                  // qq sub-group
    const int tloc = tid - (sub << 8) - (sub << 6); // tid - sub*320
    const int t0A = b << 4, t0B = (63 - b) << 4;
    const int cA = (t0A + 16) >> 2;                 // 4..128 chunks for tile A
    const int cB = 260 - cA;                        // chunks for tile B
    const bool active = tloc < 260;
    const bool isA = tloc < cA;
    const int t0 = isA ? t0A : t0B;
    const int nb = (isA ? tloc : (tloc - cA)) << 2; // n-chunk base
    const int ab = 16 + t0 - nb;                    // aligned sF read base

    const float4 z4 = make_float4(0.f, 0.f, 0.f, 0.f);

    // ---- stage this half's 8 Fx rows (front zero-padded) — k1-independent ----
    float4* dF = (float4*)smem;
    for (int idx = tid; idx < 8 * NF4; idx += 640) {
        const int qq = idx / NF4, i = idx - qq * NF4;
        const int rs = (half << 3) + qq;
        float4 v = z4;
        if (i >= 5 && i < 261)
            v = ((const float4*)Fx)[(((rs << 2) + e) << 8) + i - 5];
        dF[qq * NF4 + i] = v;
    }
    __syncthreads();

    // ---- wait for k1 (g_cw + out zero-init), then compute directly ----
    asm volatile("griddepcontrol.wait;" ::: "memory");

    // ---- compute: 4 rs rows per thread; cw straight from L2/L1 via LDG ----
    float acc[16];
#pragma unroll
    for (int j = 0; j < 16; j++) acc[j] = 0.f;

    if (active) {
        const float4* wG = (const float4*)
            (g_cw + (((half << 3) + (sub << 2)) << 10) + nb); // row stride 1024
        const float* fBase = &smem[(sub << 2) * SFQ + ab];
#pragma unroll
        for (int qq = 0; qq < 4; qq++) {
            const float4 w = __ldg(wG + (qq << 8));           // (qq*1024)/4
            const float4* F4 = (const float4*)(fBase + qq * SFQ);
            float ff[24];
#pragma unroll
            for (int m = 0; m < 6; m++) {
                const float4 v = F4[m];
                ff[4 * m + 0] = v.x; ff[4 * m + 1] = v.y;
                ff[4 * m + 2] = v.z; ff[4 * m + 3] = v.w;
            }
#pragma unroll
            for (int j = 0; j < 16; j++)
                acc[j] += ff[4 + j] * w.x + ff[3 + j] * w.y
                        + ff[2 + j] * w.z + ff[1 + j] * w.w;
        }
    }
    __syncthreads();

    // ---- per-chunk partials overlay the staging buffer ----
    // per sub-group: [16][128] (tile A) then [16][256] (tile B)
    float* redA = smem + sub * RSEG;
    float* redB = redA + 16 * 128;
    if (active) {
        if (isA) {
#pragma unroll
            for (int j = 0; j < 16; j++) redA[j * 128 + tloc] = acc[j];
        } else {
#pragma unroll
            for (int j = 0; j < 16; j++) redB[j * 256 + (tloc - cA)] = acc[j];
        }
    }
    __syncthreads();

    // ---- reduce: 32 rows x 16 lanes, shuffle within 16-lane groups ----
    if (tid < 512) {
        const int row = tid >> 4, k = tid & 15;
        float s = 0.f;
        if (row < 16) {
            for (int c = k; c < cA; c += 16)
                s += smem[row * 128 + c] + smem[RSEG + row * 128 + c];
        } else {
            const int r2 = row - 16;
            for (int c = k; c < cB; c += 16)
                s += smem[2048 + r2 * 256 + c] + smem[RSEG + 2048 + r2 * 256 + c];
        }
#pragma unroll
        for (int o = 8; o; o >>= 1) s += __shfl_xor_sync(0xffffffffu, s, o);

        if (k == 0) {
            const int t = (row < 16) ? (t0A + row) : (t0B + row - 16);
            atomicAdd(&out[(t << 2) + e], s);   // 2 contributors: deterministic
        }
    }
}

// ---------------------------------------------------------------------------
extern "C" void kernel_launch(void* const* d_in, const int* in_sizes, int n_in,
                              void* d_out, int out_size) {
    const float* Fx  = (const float*)d_in[0];   // [4,4,4,1024]
    const float* Dis = (const float*)d_in[1];   // [4,1024]
    const float* w0  = (const float*)d_in[2];   // [4,4,1024]
    float* out = (float*)d_out;                 // [1024*4 anti | 1024 gamma]

    k1<<<8, 256>>>(Fx, Dis, w0, out);

    // k2 with programmatic dependent launch (overlaps with k1)
    const size_t dynBytes = (size_t)(2 * RSEG) * sizeof(float);  // 49,152 B
    cudaLaunchConfig_t cfg = {};
    cfg.gridDim = dim3(32, 4, 2);
    cfg.blockDim = dim3(640);
    cfg.dynamicSmemBytes = dynBytes;
    cfg.stream = 0;
    cudaLaunchAttribute attr[1];
    attr[0].id = cudaLaunchAttributeProgrammaticStreamSerialization;
    attr[0].val.programmaticStreamSerializationAllowed = 1;
    cfg.attrs = attr;
    cfg.numAttrs = 1;
    cudaLaunchKernelEx(&cfg, k2, Fx, out);
}